// round 2
// baseline (speedup 1.0000x reference)
#include <cuda_runtime.h>
#include <cuda_bf16.h>
#include <cstddef>
#include <cstdint>

#define T_LEN 512
#define B_SZ  256
#define I_SZ  128
#define H_SZ  256
#define G3H   768   // 3*H
#define HB    (B_SZ * H_SZ)
#define NCTA_REC 128

// ---------------------------------------------------------------------------
// Scratch (device globals; no dynamic allocation anywhere)
// ---------------------------------------------------------------------------
__device__ __nv_bfloat16 g_xh[(size_t)T_LEN * B_SZ * I_SZ];
__device__ __nv_bfloat16 g_xl[(size_t)T_LEN * B_SZ * I_SZ];
__device__ __nv_bfloat16 g_h1h[(size_t)T_LEN * HB];   // layer0 output sequence (hi split)
__device__ __nv_bfloat16 g_h1l[(size_t)T_LEN * HB];   // layer0 output sequence (lo split)
__device__ float         g_G[(size_t)T_LEN * B_SZ * G3H];  // gate preactivations (reused per layer)
__device__ __nv_bfloat16 g_ping_h[2 * HB];            // layer1 ping-pong hidden (hi)
__device__ __nv_bfloat16 g_ping_l[2 * HB];            // layer1 ping-pong hidden (lo)
__device__ __nv_bfloat16 g_zh[HB], g_zl[HB];          // zero h0 input
__device__ float         g_hfinal[HB];                // last h2 (fp32) for FC
__device__ unsigned      g_ctr[T_LEN];                // per-step barrier counters
// weight splits
__device__ __nv_bfloat16 g_Wih0h[G3H * I_SZ], g_Wih0l[G3H * I_SZ];
__device__ __nv_bfloat16 g_Whh0h[G3H * H_SZ], g_Whh0l[G3H * H_SZ];
__device__ __nv_bfloat16 g_Wih1h[G3H * H_SZ], g_Wih1l[G3H * H_SZ];
__device__ __nv_bfloat16 g_Whh1h[G3H * H_SZ], g_Whh1l[G3H * H_SZ];

// ---------------------------------------------------------------------------
// Helpers
// ---------------------------------------------------------------------------
__device__ __forceinline__ void split_bf16(float v, __nv_bfloat16& hi, __nv_bfloat16& lo) {
    __nv_bfloat16 h = __float2bfloat16(v);
    hi = h;
    lo = __float2bfloat16(v - __bfloat162float(h));
}

// mma.sync m16n8k16 row.col bf16 -> f32
__device__ __forceinline__ void mma16816(float* c, const unsigned* a, const unsigned* b) {
    asm volatile(
        "mma.sync.aligned.m16n8k16.row.col.f32.bf16.bf16.f32 "
        "{%0,%1,%2,%3}, {%4,%5,%6,%7}, {%8,%9}, {%0,%1,%2,%3};\n"
        : "+f"(c[0]), "+f"(c[1]), "+f"(c[2]), "+f"(c[3])
        : "r"(a[0]), "r"(a[1]), "r"(a[2]), "r"(a[3]), "r"(b[0]), "r"(b[1]));
}

// Load A fragment (16x16) from row-major [rows, ld], pre-offset to tile origin.
__device__ __forceinline__ void ldfragA(unsigned* a, const __nv_bfloat16* __restrict__ A, int ld) {
    int lane = threadIdx.x & 31;
    int g = lane >> 2, tq = lane & 3;
    const __nv_bfloat16* p = A + (size_t)g * ld + 2 * tq;
    a[0] = *reinterpret_cast<const unsigned*>(p);
    a[1] = *reinterpret_cast<const unsigned*>(p + (size_t)8 * ld);
    a[2] = *reinterpret_cast<const unsigned*>(p + 8);
    a[3] = *reinterpret_cast<const unsigned*>(p + (size_t)8 * ld + 8);
}

// Load B fragment (n=8, k=16) from W stored [N, K] row-major ("col" layout for mma).
__device__ __forceinline__ void ldfragB(unsigned* b, const __nv_bfloat16* __restrict__ Bp, int ld) {
    int lane = threadIdx.x & 31;
    int g = lane >> 2, tq = lane & 3;
    const __nv_bfloat16* p = Bp + (size_t)g * ld + 2 * tq;
    b[0] = *reinterpret_cast<const unsigned*>(p);
    b[1] = *reinterpret_cast<const unsigned*>(p + 8);
}

// ---------------------------------------------------------------------------
// Split kernels
// ---------------------------------------------------------------------------
__global__ void k_split_w(const float* __restrict__ wih0, const float* __restrict__ whh0,
                          const float* __restrict__ wih1, const float* __restrict__ whh1) {
    const int n0 = G3H * I_SZ;
    const int n1 = G3H * H_SZ;
    const int total = n0 + 3 * n1;
    for (int i = blockIdx.x * blockDim.x + threadIdx.x; i < total; i += gridDim.x * blockDim.x) {
        if (i < n0) {
            split_bf16(wih0[i], g_Wih0h[i], g_Wih0l[i]);
        } else if (i < n0 + n1) {
            int j = i - n0;
            split_bf16(whh0[j], g_Whh0h[j], g_Whh0l[j]);
        } else if (i < n0 + 2 * n1) {
            int j = i - n0 - n1;
            split_bf16(wih1[j], g_Wih1h[j], g_Wih1l[j]);
        } else {
            int j = i - n0 - 2 * n1;
            split_bf16(whh1[j], g_Whh1h[j], g_Whh1l[j]);
        }
    }
}

__global__ void k_split_x(const float* __restrict__ x) {
    const int n = T_LEN * B_SZ * I_SZ;
    for (int i = blockIdx.x * blockDim.x + threadIdx.x; i < n; i += gridDim.x * blockDim.x) {
        split_bf16(x[i], g_xh[i], g_xl[i]);
    }
}

// Zero barrier counters + zero-h0 buffers (run before each recurrence kernel)
__global__ void k_zero() {
    int i = blockIdx.x * blockDim.x + threadIdx.x;
    if (i < T_LEN) g_ctr[i] = 0u;
    if (i < HB) {
        g_zh[i] = __float2bfloat16(0.0f);
        g_zl[i] = __float2bfloat16(0.0f);
    }
}

// ---------------------------------------------------------------------------
// Feedforward gate GEMM: G[M,768] = A[M,K] @ W^T + b_ih  (split bf16, 3-term)
// Grid: M/64 CTAs; each CTA loops over the 12 n-tiles of 64 so A stays L1-hot.
// 256 threads = 8 warps (2 m-groups x 4 n-groups), warp tile 32x16.
// ---------------------------------------------------------------------------
__global__ void __launch_bounds__(256) k_gi(
    const __nv_bfloat16* __restrict__ Ah, const __nv_bfloat16* __restrict__ Al, int K,
    const __nv_bfloat16* __restrict__ Wh, const __nv_bfloat16* __restrict__ Wl,
    const float* __restrict__ bias, float* __restrict__ Gout) {
    int w = threadIdx.x >> 5;
    int lane = threadIdx.x & 31;
    int g = lane >> 2, tq = lane & 3;
    int m0 = blockIdx.x * 64 + (w >> 2) * 32;   // warp M origin
    int nw = (w & 3) * 16;                      // warp offset within n-tile

#pragma unroll 1
    for (int nt = 0; nt < G3H / 64; nt++) {
        int n0 = nt * 64 + nw;
        float acc[2][2][4];
#pragma unroll
        for (int a = 0; a < 2; a++)
#pragma unroll
            for (int b = 0; b < 2; b++)
#pragma unroll
                for (int i = 0; i < 4; i++) acc[a][b][i] = 0.0f;

#pragma unroll 4
        for (int k = 0; k < K; k += 16) {
            unsigned aH[2][4], aL[2][4], bH[2][2], bL[2][2];
#pragma unroll
            for (int ms = 0; ms < 2; ms++) {
                ldfragA(aH[ms], Ah + (size_t)(m0 + ms * 16) * K + k, K);
                ldfragA(aL[ms], Al + (size_t)(m0 + ms * 16) * K + k, K);
            }
#pragma unroll
            for (int ns = 0; ns < 2; ns++) {
                ldfragB(bH[ns], Wh + (size_t)(n0 + ns * 8) * K + k, K);
                ldfragB(bL[ns], Wl + (size_t)(n0 + ns * 8) * K + k, K);
            }
#pragma unroll
            for (int ms = 0; ms < 2; ms++)
#pragma unroll
                for (int ns = 0; ns < 2; ns++) {
                    mma16816(acc[ms][ns], aH[ms], bH[ns]);
                    mma16816(acc[ms][ns], aH[ms], bL[ns]);
                    mma16816(acc[ms][ns], aL[ms], bH[ns]);
                }
        }

#pragma unroll
        for (int ms = 0; ms < 2; ms++)
#pragma unroll
            for (int ns = 0; ns < 2; ns++)
#pragma unroll
                for (int i = 0; i < 4; i++) {
                    int row = m0 + ms * 16 + g + ((i & 2) ? 8 : 0);
                    int col = n0 + ns * 8 + tq * 2 + (i & 1);
                    Gout[(size_t)row * G3H + col] = acc[ms][ns][i] + bias[col];
                }
    }
}

// ---------------------------------------------------------------------------
// Persistent GRU recurrence: one launch per layer, loops over all T steps with
// a software global barrier between steps. 128 CTAs (all co-resident), 128 thr.
// CTA (bb, jb): batch rows [bb*32, +32), hidden units [jb*16, +16), all 3 gates.
// fp32 h lives in registers across steps; only bf16 splits hit memory.
// ---------------------------------------------------------------------------
__global__ void __launch_bounds__(128) k_rec(
    const float* __restrict__ G,                   // [T, B, 768] (includes b_ih)
    const __nv_bfloat16* __restrict__ Wh, const __nv_bfloat16* __restrict__ Wl,  // [768,256]
    const float* __restrict__ b_hh,
    const __nv_bfloat16* __restrict__ h0h, const __nv_bfloat16* __restrict__ h0l, // zeros
    __nv_bfloat16* __restrict__ bufh, __nv_bfloat16* __restrict__ bufl,
    int seq_mode,                                  // 1: buf indexed by t (layer0); 0: ping-pong
    float* __restrict__ hfinal) {                  // null or [B,H]
    int w = threadIdx.x >> 5;
    int lane = threadIdx.x & 31;
    int g = lane >> 2, tq = lane & 3;
    int bb = blockIdx.x >> 4;        // 0..7  batch block (32 rows)
    int jb = blockIdx.x & 15;        // 0..15 hidden block (16 units)
    int m0 = bb * 32 + (w >> 1) * 16;
    int j0 = jb * 16 + (w & 1) * 8;
    int c0 = j0 + tq * 2;
    int row_lo = m0 + g, row_hi = m0 + g + 8;

    // cache b_hh for this thread's two columns
    float bR[2] = {b_hh[c0], b_hh[c0 + 1]};
    float bZ[2] = {b_hh[H_SZ + c0], b_hh[H_SZ + c0 + 1]};
    float bN[2] = {b_hh[2 * H_SZ + c0], b_hh[2 * H_SZ + c0 + 1]};

    float hprev[4] = {0.0f, 0.0f, 0.0f, 0.0f};

#pragma unroll 1
    for (int t = 0; t < T_LEN; t++) {
        const __nv_bfloat16 *hin_h, *hin_l;
        __nv_bfloat16 *hout_h, *hout_l;
        if (seq_mode) {
            hin_h  = (t == 0) ? h0h : bufh + (size_t)(t - 1) * HB;
            hin_l  = (t == 0) ? h0l : bufl + (size_t)(t - 1) * HB;
            hout_h = bufh + (size_t)t * HB;
            hout_l = bufl + (size_t)t * HB;
        } else {
            hin_h  = (t == 0) ? h0h : bufh + (size_t)(t & 1) * HB;
            hin_l  = (t == 0) ? h0l : bufl + (size_t)(t & 1) * HB;
            hout_h = bufh + (size_t)((t + 1) & 1) * HB;
            hout_l = bufl + (size_t)((t + 1) & 1) * HB;
        }

        float accR[4] = {0, 0, 0, 0}, accZ[4] = {0, 0, 0, 0}, accN[4] = {0, 0, 0, 0};
#pragma unroll
        for (int k = 0; k < H_SZ; k += 16) {
            unsigned ah[4], al[4];
            ldfragA(ah, hin_h + (size_t)m0 * H_SZ + k, H_SZ);
            ldfragA(al, hin_l + (size_t)m0 * H_SZ + k, H_SZ);
            unsigned bRh[2], bRl[2], bZh[2], bZl[2], bNh[2], bNl[2];
            ldfragB(bRh, Wh + (size_t)(0 * H_SZ + j0) * H_SZ + k, H_SZ);
            ldfragB(bZh, Wh + (size_t)(1 * H_SZ + j0) * H_SZ + k, H_SZ);
            ldfragB(bNh, Wh + (size_t)(2 * H_SZ + j0) * H_SZ + k, H_SZ);
            ldfragB(bRl, Wl + (size_t)(0 * H_SZ + j0) * H_SZ + k, H_SZ);
            ldfragB(bZl, Wl + (size_t)(1 * H_SZ + j0) * H_SZ + k, H_SZ);
            ldfragB(bNl, Wl + (size_t)(2 * H_SZ + j0) * H_SZ + k, H_SZ);
            mma16816(accR, ah, bRh); mma16816(accR, ah, bRl); mma16816(accR, al, bRh);
            mma16816(accZ, ah, bZh); mma16816(accZ, ah, bZl); mma16816(accZ, al, bZh);
            mma16816(accN, ah, bNh); mma16816(accN, ah, bNl); mma16816(accN, al, bNh);
        }

        const float* Gt = G + (size_t)t * B_SZ * G3H;
#pragma unroll
        for (int i = 0; i < 4; i++) {
            int row = (i & 2) ? row_hi : row_lo;
            int col = c0 + (i & 1);
            float ir  = Gt[(size_t)row * G3H + col];
            float iz  = Gt[(size_t)row * G3H + H_SZ + col];
            float in_ = Gt[(size_t)row * G3H + 2 * H_SZ + col];
            float hr = accR[i] + bR[i & 1];
            float hz = accZ[i] + bZ[i & 1];
            float hn = accN[i] + bN[i & 1];
            float r = 1.0f / (1.0f + expf(-(ir + hr)));
            float z = 1.0f / (1.0f + expf(-(iz + hz)));
            float n = tanhf(in_ + r * hn);
            float v = (1.0f - z) * n + z * hprev[i];
            hprev[i] = v;
            __nv_bfloat16 vh, vl;
            split_bf16(v, vh, vl);
            size_t o = (size_t)row * H_SZ + col;
            hout_h[o] = vh;
            hout_l[o] = vl;
            if (hfinal != nullptr && t == T_LEN - 1) hfinal[o] = v;
        }

        // --- software global barrier for step t ---
        __syncthreads();                       // all CTA stores issued
        if (threadIdx.x == 0) {
            __threadfence();                   // publish (release)
            atomicAdd(&g_ctr[t], 1u);
            volatile unsigned* c = &g_ctr[t];
            while (*c < NCTA_REC) {}
            __threadfence();                   // acquire
        }
        __syncthreads();
    }
}

// ---------------------------------------------------------------------------
// Final FC: out[B,H] = h2 @ W_fc^T + b_fc (fp32, tiny)
// ---------------------------------------------------------------------------
__global__ void __launch_bounds__(256) k_fc(const float* __restrict__ Wfc,
                                            const float* __restrict__ bfc,
                                            float* __restrict__ out) {
    __shared__ float hrow[H_SZ];
    int b_ = blockIdx.x, j = threadIdx.x;
    hrow[j] = g_hfinal[(size_t)b_ * H_SZ + j];
    __syncthreads();
    const float* wr = Wfc + (size_t)j * H_SZ;
    float s = bfc[j];
#pragma unroll 8
    for (int k = 0; k < H_SZ; k++) s += hrow[k] * wr[k];
    out[(size_t)b_ * H_SZ + j] = s;
}

// ---------------------------------------------------------------------------
// Launch
// ---------------------------------------------------------------------------
extern "C" void kernel_launch(void* const* d_in, const int* in_sizes, int n_in,
                              void* d_out, int out_size) {
    const float* x    = (const float*)d_in[0];
    const float* Wih0 = (const float*)d_in[1];
    const float* Whh0 = (const float*)d_in[2];
    const float* bih0 = (const float*)d_in[3];
    const float* bhh0 = (const float*)d_in[4];
    const float* Wih1 = (const float*)d_in[5];
    const float* Whh1 = (const float*)d_in[6];
    const float* bih1 = (const float*)d_in[7];
    const float* bhh1 = (const float*)d_in[8];
    const float* Wfc  = (const float*)d_in[9];
    const float* bfc  = (const float*)d_in[10];
    (void)in_sizes; (void)n_in; (void)out_size;

    void *p_xh, *p_xl, *p_h1h, *p_h1l, *p_G, *p_ph, *p_pl, *p_zh, *p_zl, *p_hf;
    void *p_Wih0h, *p_Wih0l, *p_Whh0h, *p_Whh0l, *p_Wih1h, *p_Wih1l, *p_Whh1h, *p_Whh1l;
    cudaGetSymbolAddress(&p_xh, g_xh);       cudaGetSymbolAddress(&p_xl, g_xl);
    cudaGetSymbolAddress(&p_h1h, g_h1h);     cudaGetSymbolAddress(&p_h1l, g_h1l);
    cudaGetSymbolAddress(&p_G, g_G);
    cudaGetSymbolAddress(&p_ph, g_ping_h);   cudaGetSymbolAddress(&p_pl, g_ping_l);
    cudaGetSymbolAddress(&p_zh, g_zh);       cudaGetSymbolAddress(&p_zl, g_zl);
    cudaGetSymbolAddress(&p_hf, g_hfinal);
    cudaGetSymbolAddress(&p_Wih0h, g_Wih0h); cudaGetSymbolAddress(&p_Wih0l, g_Wih0l);
    cudaGetSymbolAddress(&p_Whh0h, g_Whh0h); cudaGetSymbolAddress(&p_Whh0l, g_Whh0l);
    cudaGetSymbolAddress(&p_Wih1h, g_Wih1h); cudaGetSymbolAddress(&p_Wih1l, g_Wih1l);
    cudaGetSymbolAddress(&p_Whh1h, g_Whh1h); cudaGetSymbolAddress(&p_Whh1l, g_Whh1l);

    typedef __nv_bfloat16 bf;
    float* G = (float*)p_G;

    // 1) splits
    k_split_w<<<512, 256>>>(Wih0, Whh0, Wih1, Whh1);
    k_split_x<<<2048, 256>>>(x);

    // 2) layer-0 feedforward gates
    k_gi<<<T_LEN * B_SZ / 64, 256>>>((bf*)p_xh, (bf*)p_xl, I_SZ,
                                     (bf*)p_Wih0h, (bf*)p_Wih0l, bih0, G);

    // 3) layer-0 recurrence (persistent, writes h1 sequence splits)
    k_zero<<<(HB + 255) / 256, 256>>>();
    k_rec<<<NCTA_REC, 128>>>(G, (bf*)p_Whh0h, (bf*)p_Whh0l, bhh0,
                             (bf*)p_zh, (bf*)p_zl,
                             (bf*)p_h1h, (bf*)p_h1l, /*seq_mode=*/1, nullptr);

    // 4) layer-1 feedforward gates
    k_gi<<<T_LEN * B_SZ / 64, 256>>>((bf*)p_h1h, (bf*)p_h1l, H_SZ,
                                     (bf*)p_Wih1h, (bf*)p_Wih1l, bih1, G);

    // 5) layer-1 recurrence (persistent, ping-pong, emits final fp32 h)
    k_zero<<<(HB + 255) / 256, 256>>>();
    k_rec<<<NCTA_REC, 128>>>(G, (bf*)p_Whh1h, (bf*)p_Whh1l, bhh1,
                             (bf*)p_zh, (bf*)p_zl,
                             (bf*)p_ph, (bf*)p_pl, /*seq_mode=*/0, (float*)p_hf);

    // 6) final FC
    k_fc<<<B_SZ, H_SZ>>>(Wfc, bfc, (float*)d_out);
}

// round 3
// speedup vs baseline: 1.2396x; 1.2396x over previous
#include <cuda_runtime.h>
#include <cuda_bf16.h>
#include <cstddef>
#include <cstdint>

#define T_LEN 512
#define B_SZ  256
#define I_SZ  128
#define H_SZ  256
#define G3H   768   // 3*H
#define HB    (B_SZ * H_SZ)
#define NGRP  4              // batch groups (64 rows each)
#define GRP_CTAS 16          // CTAs per batch group (hidden blocks)
#define WPITCH 264           // smem weight row pitch (bank-conflict-free)
#define SMEM_REC_BYTES (6 * 16 * WPITCH * 2)   // 50688

// ---------------------------------------------------------------------------
// Scratch (device globals; no dynamic allocation anywhere)
// ---------------------------------------------------------------------------
__device__ __nv_bfloat16 g_xh[(size_t)T_LEN * B_SZ * I_SZ];
__device__ __nv_bfloat16 g_xl[(size_t)T_LEN * B_SZ * I_SZ];
__device__ __nv_bfloat16 g_h1h[(size_t)T_LEN * HB];   // layer0 output sequence (hi split)
__device__ __nv_bfloat16 g_h1l[(size_t)T_LEN * HB];   // layer0 output sequence (lo split)
__device__ float         g_G[(size_t)T_LEN * B_SZ * G3H];  // gate preactivations
__device__ __nv_bfloat16 g_ping_h[2 * HB];            // layer1 ping-pong hidden (hi)
__device__ __nv_bfloat16 g_ping_l[2 * HB];            // layer1 ping-pong hidden (lo)
__device__ float         g_hfinal[HB];                // last h2 (fp32) for FC
__device__ unsigned      g_flag[2][T_LEN * NGRP];     // per-(layer, t, batch-group) flags
// weight splits
__device__ __nv_bfloat16 g_Wih0h[G3H * I_SZ], g_Wih0l[G3H * I_SZ];
__device__ __nv_bfloat16 g_Whh0h[G3H * H_SZ], g_Whh0l[G3H * H_SZ];
__device__ __nv_bfloat16 g_Wih1h[G3H * H_SZ], g_Wih1l[G3H * H_SZ];
__device__ __nv_bfloat16 g_Whh1h[G3H * H_SZ], g_Whh1l[G3H * H_SZ];

// ---------------------------------------------------------------------------
// Helpers
// ---------------------------------------------------------------------------
__device__ __forceinline__ void split_bf16(float v, __nv_bfloat16& hi, __nv_bfloat16& lo) {
    __nv_bfloat16 h = __float2bfloat16(v);
    hi = h;
    lo = __float2bfloat16(v - __bfloat162float(h));
}

__device__ __forceinline__ void mma16816(float* c, const unsigned* a, const unsigned* b) {
    asm volatile(
        "mma.sync.aligned.m16n8k16.row.col.f32.bf16.bf16.f32 "
        "{%0,%1,%2,%3}, {%4,%5,%6,%7}, {%8,%9}, {%0,%1,%2,%3};\n"
        : "+f"(c[0]), "+f"(c[1]), "+f"(c[2]), "+f"(c[3])
        : "r"(a[0]), "r"(a[1]), "r"(a[2]), "r"(a[3]), "r"(b[0]), "r"(b[1]));
}

// A fragment (16x16) from global row-major [rows, ld], pre-offset to tile origin.
__device__ __forceinline__ void ldfragA(unsigned* a, const __nv_bfloat16* __restrict__ A, int ld) {
    int lane = threadIdx.x & 31;
    int g = lane >> 2, tq = lane & 3;
    const __nv_bfloat16* p = A + (size_t)g * ld + 2 * tq;
    a[0] = *reinterpret_cast<const unsigned*>(p);
    a[1] = *reinterpret_cast<const unsigned*>(p + (size_t)8 * ld);
    a[2] = *reinterpret_cast<const unsigned*>(p + 8);
    a[3] = *reinterpret_cast<const unsigned*>(p + (size_t)8 * ld + 8);
}

// B fragment (n=8, k=16) from global [N, K] row-major.
__device__ __forceinline__ void ldfragB(unsigned* b, const __nv_bfloat16* __restrict__ Bp, int ld) {
    int lane = threadIdx.x & 31;
    int g = lane >> 2, tq = lane & 3;
    const __nv_bfloat16* p = Bp + (size_t)g * ld + 2 * tq;
    b[0] = *reinterpret_cast<const unsigned*>(p);
    b[1] = *reinterpret_cast<const unsigned*>(p + 8);
}

// B fragment from pitched smem (row0 pre-offset to the warp's 8-row group).
__device__ __forceinline__ void ldfragB_s(unsigned* b, const __nv_bfloat16* p) {
    int lane = threadIdx.x & 31;
    int g = lane >> 2, tq = lane & 3;
    const __nv_bfloat16* q = p + g * WPITCH + 2 * tq;
    b[0] = *reinterpret_cast<const unsigned*>(q);
    b[1] = *reinterpret_cast<const unsigned*>(q + 8);
}

// ---------------------------------------------------------------------------
// Setup kernels
// ---------------------------------------------------------------------------
__global__ void k_zero() {
    int i = blockIdx.x * blockDim.x + threadIdx.x;
    if (i < 2 * T_LEN * NGRP) ((unsigned*)g_flag)[i] = 0u;
}

__global__ void k_dummy() {}

__global__ void k_split_w(const float* __restrict__ wih0, const float* __restrict__ whh0,
                          const float* __restrict__ wih1, const float* __restrict__ whh1) {
    const int n0 = G3H * I_SZ;
    const int n1 = G3H * H_SZ;
    const int total = n0 + 3 * n1;
    for (int i = blockIdx.x * blockDim.x + threadIdx.x; i < total; i += gridDim.x * blockDim.x) {
        if (i < n0) {
            split_bf16(wih0[i], g_Wih0h[i], g_Wih0l[i]);
        } else if (i < n0 + n1) {
            int j = i - n0;
            split_bf16(whh0[j], g_Whh0h[j], g_Whh0l[j]);
        } else if (i < n0 + 2 * n1) {
            int j = i - n0 - n1;
            split_bf16(wih1[j], g_Wih1h[j], g_Wih1l[j]);
        } else {
            int j = i - n0 - 2 * n1;
            split_bf16(whh1[j], g_Whh1h[j], g_Whh1l[j]);
        }
    }
}

__global__ void k_split_x(const float* __restrict__ x) {
    const int n = T_LEN * B_SZ * I_SZ;
    for (int i = blockIdx.x * blockDim.x + threadIdx.x; i < n; i += gridDim.x * blockDim.x) {
        split_bf16(x[i], g_xh[i], g_xl[i]);
    }
}

// ---------------------------------------------------------------------------
// Feedforward gate GEMM: G[M,768] = A[M,K] @ W^T + b_ih  (split bf16, 3-term)
// ---------------------------------------------------------------------------
__global__ void __launch_bounds__(256) k_gi(
    const __nv_bfloat16* __restrict__ Ah, const __nv_bfloat16* __restrict__ Al, int K,
    const __nv_bfloat16* __restrict__ Wh, const __nv_bfloat16* __restrict__ Wl,
    const float* __restrict__ bias, float* __restrict__ Gout) {
    int w = threadIdx.x >> 5;
    int lane = threadIdx.x & 31;
    int g = lane >> 2, tq = lane & 3;
    int m0 = blockIdx.x * 64 + (w >> 2) * 32;
    int nw = (w & 3) * 16;

#pragma unroll 1
    for (int nt = 0; nt < G3H / 64; nt++) {
        int n0 = nt * 64 + nw;
        float acc[2][2][4];
#pragma unroll
        for (int a = 0; a < 2; a++)
#pragma unroll
            for (int b = 0; b < 2; b++)
#pragma unroll
                for (int i = 0; i < 4; i++) acc[a][b][i] = 0.0f;

#pragma unroll 4
        for (int k = 0; k < K; k += 16) {
            unsigned aH[2][4], aL[2][4], bH[2][2], bL[2][2];
#pragma unroll
            for (int ms = 0; ms < 2; ms++) {
                ldfragA(aH[ms], Ah + (size_t)(m0 + ms * 16) * K + k, K);
                ldfragA(aL[ms], Al + (size_t)(m0 + ms * 16) * K + k, K);
            }
#pragma unroll
            for (int ns = 0; ns < 2; ns++) {
                ldfragB(bH[ns], Wh + (size_t)(n0 + ns * 8) * K + k, K);
                ldfragB(bL[ns], Wl + (size_t)(n0 + ns * 8) * K + k, K);
            }
#pragma unroll
            for (int ms = 0; ms < 2; ms++)
#pragma unroll
                for (int ns = 0; ns < 2; ns++) {
                    mma16816(acc[ms][ns], aH[ms], bH[ns]);
                    mma16816(acc[ms][ns], aH[ms], bL[ns]);
                    mma16816(acc[ms][ns], aL[ms], bH[ns]);
                }
        }

#pragma unroll
        for (int ms = 0; ms < 2; ms++)
#pragma unroll
            for (int ns = 0; ns < 2; ns++)
#pragma unroll
                for (int i = 0; i < 4; i++) {
                    int row = m0 + ms * 16 + g + ((i & 2) ? 8 : 0);
                    int col = n0 + ns * 8 + tq * 2 + (i & 1);
                    Gout[(size_t)row * G3H + col] = acc[ms][ns][i] + bias[col];
                }
    }
}

// ---------------------------------------------------------------------------
// Persistent GRU recurrence. Grid: 64 CTAs = 4 batch-groups x 16 hidden blocks.
// 256 threads (8 warps: 4 batch-quarters x 2 hidden-halves).
// CTA tile: 64 batch x 16 hidden x 3 gates. Weights smem-resident (loaded once).
// Sync: per-(t, batch-group) 16-CTA flag (release/acquire through L2).
// ---------------------------------------------------------------------------
__global__ void __launch_bounds__(256) k_rec(
    const float* __restrict__ G,
    const __nv_bfloat16* __restrict__ Wh, const __nv_bfloat16* __restrict__ Wl,  // [768,256]
    const float* __restrict__ b_hh,
    __nv_bfloat16* __restrict__ bufh, __nv_bfloat16* __restrict__ bufl,
    int seq_mode,                           // 1: buf indexed by t; 0: ping-pong
    float* __restrict__ hfinal,             // null or [B,H]
    unsigned* __restrict__ flags) {         // [T, NGRP]
    extern __shared__ __nv_bfloat16 s_w[];  // [6][16][WPITCH]: (gate*2+split)

    const int tid = threadIdx.x;
    const int w = tid >> 5, lane = tid & 31;
    const int g = lane >> 2, tq = lane & 3;
    const int bb = blockIdx.x >> 4;          // 0..3 batch group (64 rows)
    const int jb = blockIdx.x & 15;          // 0..15 hidden block (16 units)
    const int mq = w >> 1, nh = w & 1;
    const int m0 = bb * 64 + mq * 16;
    const int j0 = jb * 16 + nh * 8;
    const int c0 = j0 + tq * 2;
    const int row_lo = m0 + g, row_hi = m0 + g + 8;

    // ---- stage this CTA's weight slice into smem (once) ----
#pragma unroll 1
    for (int s = 0; s < 2; s++) {
        const __nv_bfloat16* Wsrc = s ? Wl : Wh;
#pragma unroll 1
        for (int gate = 0; gate < 3; gate++) {
            const unsigned* src = reinterpret_cast<const unsigned*>(
                Wsrc + (size_t)(gate * H_SZ + jb * 16) * H_SZ);
            __nv_bfloat16* dst = s_w + (size_t)(gate * 2 + s) * 16 * WPITCH;
            for (int idx = tid; idx < 16 * 128; idx += 256) {
                int r = idx >> 7, cu = idx & 127;
                *reinterpret_cast<unsigned*>(dst + r * WPITCH + cu * 2) = src[r * 128 + cu];
            }
        }
    }
    __syncthreads();

    // per-thread b_hh for its two columns
    float bR[2] = {b_hh[c0], b_hh[c0 + 1]};
    float bZ[2] = {b_hh[H_SZ + c0], b_hh[H_SZ + c0 + 1]};
    float bN[2] = {b_hh[2 * H_SZ + c0], b_hh[2 * H_SZ + c0 + 1]};

    float hprev[4] = {0.0f, 0.0f, 0.0f, 0.0f};

#pragma unroll 1
    for (int t = 0; t < T_LEN; t++) {
        // ---- prefetch gate preactivations (independent of h; hides DRAM) ----
        const float* Gt = G + (size_t)t * B_SZ * G3H;
        float gir[4], giz[4], gin[4];
#pragma unroll
        for (int i = 0; i < 4; i++) {
            int row = (i & 2) ? row_hi : row_lo;
            const float* p = Gt + (size_t)row * G3H + c0 + (i & 1);
            gir[i] = __ldg(p);
            giz[i] = __ldg(p + H_SZ);
            gin[i] = __ldg(p + 2 * H_SZ);
        }

        // ---- wait for previous step of this batch group ----
        if (t > 0) {
            if (tid == 0) {
                const unsigned* fp = flags + (size_t)(t - 1) * NGRP + bb;
                unsigned v;
                do {
                    asm volatile("ld.acquire.gpu.global.u32 %0, [%1];" : "=r"(v) : "l"(fp));
                } while (v < GRP_CTAS);
            }
            __syncthreads();
        }

        float accR[4] = {0, 0, 0, 0}, accZ[4] = {0, 0, 0, 0}, accN[4] = {0, 0, 0, 0};
        if (t > 0) {
            const __nv_bfloat16* hin_h;
            const __nv_bfloat16* hin_l;
            if (seq_mode) {
                hin_h = bufh + (size_t)(t - 1) * HB;
                hin_l = bufl + (size_t)(t - 1) * HB;
            } else {
                hin_h = bufh + (size_t)((t - 1) & 1) * HB;
                hin_l = bufl + (size_t)((t - 1) & 1) * HB;
            }
#pragma unroll 4
            for (int k = 0; k < H_SZ; k += 16) {
                unsigned ah[4], al[4];
                ldfragA(ah, hin_h + (size_t)m0 * H_SZ + k, H_SZ);
                ldfragA(al, hin_l + (size_t)m0 * H_SZ + k, H_SZ);
                unsigned bRh[2], bRl[2], bZh[2], bZl[2], bNh[2], bNl[2];
                const __nv_bfloat16* base = s_w + nh * 8 * WPITCH + k;
                ldfragB_s(bRh, base + (size_t)(0 * 2 + 0) * 16 * WPITCH);
                ldfragB_s(bRl, base + (size_t)(0 * 2 + 1) * 16 * WPITCH);
                ldfragB_s(bZh, base + (size_t)(1 * 2 + 0) * 16 * WPITCH);
                ldfragB_s(bZl, base + (size_t)(1 * 2 + 1) * 16 * WPITCH);
                ldfragB_s(bNh, base + (size_t)(2 * 2 + 0) * 16 * WPITCH);
                ldfragB_s(bNl, base + (size_t)(2 * 2 + 1) * 16 * WPITCH);
                mma16816(accR, ah, bRh); mma16816(accR, ah, bRl); mma16816(accR, al, bRh);
                mma16816(accZ, ah, bZh); mma16816(accZ, ah, bZl); mma16816(accZ, al, bZh);
                mma16816(accN, ah, bNh); mma16816(accN, ah, bNl); mma16816(accN, al, bNh);
            }
        }

        // ---- fused pointwise GRU update ----
        __nv_bfloat16* hout_h;
        __nv_bfloat16* hout_l;
        if (seq_mode) {
            hout_h = bufh + (size_t)t * HB;
            hout_l = bufl + (size_t)t * HB;
        } else {
            hout_h = bufh + (size_t)(t & 1) * HB;
            hout_l = bufl + (size_t)(t & 1) * HB;
        }
        float v[4];
#pragma unroll
        for (int i = 0; i < 4; i++) {
            float hr = accR[i] + bR[i & 1];
            float hz = accZ[i] + bZ[i & 1];
            float hn = accN[i] + bN[i & 1];
            float r = 1.0f / (1.0f + expf(-(gir[i] + hr)));
            float z = 1.0f / (1.0f + expf(-(giz[i] + hz)));
            float n = tanhf(gin[i] + r * hn);
            v[i] = (1.0f - z) * n + z * hprev[i];
            hprev[i] = v[i];
        }
        // packed bf16x2 stores (cols c0, c0+1 contiguous)
#pragma unroll
        for (int half = 0; half < 2; half++) {
            int row = half ? row_hi : row_lo;
            float v0 = v[half * 2 + 0], v1 = v[half * 2 + 1];
            __nv_bfloat16 h0, l0, h1, l1;
            split_bf16(v0, h0, l0);
            split_bf16(v1, h1, l1);
            size_t o = (size_t)row * H_SZ + c0;
            *reinterpret_cast<__nv_bfloat162*>(hout_h + o) = __nv_bfloat162(h0, h1);
            *reinterpret_cast<__nv_bfloat162*>(hout_l + o) = __nv_bfloat162(l0, l1);
            if (hfinal != nullptr && t == T_LEN - 1) {
                hfinal[o] = v0;
                hfinal[o + 1] = v1;
            }
        }

        // ---- arrive ----
        __syncthreads();
        if (tid == 0) {
            asm volatile("red.release.gpu.global.add.u32 [%0], 1;"
                         :: "l"(flags + (size_t)t * NGRP + bb) : "memory");
        }
    }
}

// ---------------------------------------------------------------------------
// Final FC: out[B,H] = h2 @ W_fc^T + b_fc
// ---------------------------------------------------------------------------
__global__ void __launch_bounds__(256) k_fc(const float* __restrict__ Wfc,
                                            const float* __restrict__ bfc,
                                            float* __restrict__ out) {
    __shared__ float hrow[H_SZ];
    int b_ = blockIdx.x, j = threadIdx.x;
    hrow[j] = g_hfinal[(size_t)b_ * H_SZ + j];
    __syncthreads();
    const float* wr = Wfc + (size_t)j * H_SZ;
    float s = bfc[j];
#pragma unroll 8
    for (int k = 0; k < H_SZ; k++) s += hrow[k] * wr[k];
    out[(size_t)b_ * H_SZ + j] = s;
}

// ---------------------------------------------------------------------------
// Launch
// ---------------------------------------------------------------------------
extern "C" void kernel_launch(void* const* d_in, const int* in_sizes, int n_in,
                              void* d_out, int out_size) {
    const float* x    = (const float*)d_in[0];
    const float* Wih0 = (const float*)d_in[1];
    const float* Whh0 = (const float*)d_in[2];
    const float* bih0 = (const float*)d_in[3];
    const float* bhh0 = (const float*)d_in[4];
    const float* Wih1 = (const float*)d_in[5];
    const float* Whh1 = (const float*)d_in[6];
    const float* bih1 = (const float*)d_in[7];
    const float* bhh1 = (const float*)d_in[8];
    const float* Wfc  = (const float*)d_in[9];
    const float* bfc  = (const float*)d_in[10];
    (void)in_sizes; (void)n_in; (void)out_size;

    static int smem_set = 0;
    if (!smem_set) {
        cudaFuncSetAttribute(k_rec, cudaFuncAttributeMaxDynamicSharedMemorySize, SMEM_REC_BYTES);
        smem_set = 1;
    }

    void *p_xh, *p_xl, *p_h1h, *p_h1l, *p_G, *p_ph, *p_pl, *p_hf, *p_fl;
    void *p_Wih0h, *p_Wih0l, *p_Whh0h, *p_Whh0l, *p_Wih1h, *p_Wih1l, *p_Whh1h, *p_Whh1l;
    cudaGetSymbolAddress(&p_xh, g_xh);       cudaGetSymbolAddress(&p_xl, g_xl);
    cudaGetSymbolAddress(&p_h1h, g_h1h);     cudaGetSymbolAddress(&p_h1l, g_h1l);
    cudaGetSymbolAddress(&p_G, g_G);
    cudaGetSymbolAddress(&p_ph, g_ping_h);   cudaGetSymbolAddress(&p_pl, g_ping_l);
    cudaGetSymbolAddress(&p_hf, g_hfinal);   cudaGetSymbolAddress(&p_fl, g_flag);
    cudaGetSymbolAddress(&p_Wih0h, g_Wih0h); cudaGetSymbolAddress(&p_Wih0l, g_Wih0l);
    cudaGetSymbolAddress(&p_Whh0h, g_Whh0h); cudaGetSymbolAddress(&p_Whh0l, g_Whh0l);
    cudaGetSymbolAddress(&p_Wih1h, g_Wih1h); cudaGetSymbolAddress(&p_Wih1l, g_Wih1l);
    cudaGetSymbolAddress(&p_Whh1h, g_Whh1h); cudaGetSymbolAddress(&p_Whh1l, g_Whh1l);

    typedef __nv_bfloat16 bf;
    float* G = (float*)p_G;
    unsigned* fl0 = (unsigned*)p_fl;
    unsigned* fl1 = fl0 + T_LEN * NGRP;

    // launch order chosen so ncu (-s 5 -c 1) profiles k_rec layer 0
    k_zero<<<8, 512>>>();                                            // 0
    k_split_w<<<512, 256>>>(Wih0, Whh0, Wih1, Whh1);                 // 1
    k_split_x<<<2048, 256>>>(x);                                     // 2
    k_gi<<<T_LEN * B_SZ / 64, 256>>>((bf*)p_xh, (bf*)p_xl, I_SZ,
                                     (bf*)p_Wih0h, (bf*)p_Wih0l, bih0, G);  // 3
    k_dummy<<<1, 32>>>();                                            // 4
    k_rec<<<NGRP * GRP_CTAS, 256, SMEM_REC_BYTES>>>(                 // 5  <- profiled
        G, (bf*)p_Whh0h, (bf*)p_Whh0l, bhh0,
        (bf*)p_h1h, (bf*)p_h1l, /*seq_mode=*/1, nullptr, fl0);
    k_gi<<<T_LEN * B_SZ / 64, 256>>>((bf*)p_h1h, (bf*)p_h1l, H_SZ,
                                     (bf*)p_Wih1h, (bf*)p_Wih1l, bih1, G);  // 6
    k_rec<<<NGRP * GRP_CTAS, 256, SMEM_REC_BYTES>>>(                 // 7
        G, (bf*)p_Whh1h, (bf*)p_Whh1l, bhh1,
        (bf*)p_ph, (bf*)p_pl, /*seq_mode=*/0, (float*)p_hf, fl1);
    k_fc<<<B_SZ, H_SZ>>>(Wfc, bfc, (float*)d_out);                   // 8
}

// round 4
// speedup vs baseline: 1.2457x; 1.0049x over previous
#include <cuda_runtime.h>
#include <cuda_bf16.h>
#include <cstddef>
#include <cstdint>

#define T_LEN 512
#define B_SZ  256
#define I_SZ  128
#define H_SZ  256
#define G3H   768   // 3*H
#define HB    (B_SZ * H_SZ)
#define NGRP  4              // batch groups (64 rows each)
#define GRP_CTAS 16          // CTAs per batch group (hidden blocks)
#define WPITCH 264           // smem weight row pitch (bank-conflict-free)
#define SMEM_REC_BYTES (6 * 16 * WPITCH * 2)   // 50688

// ---------------------------------------------------------------------------
// Scratch (device globals; no dynamic allocation anywhere)
// ---------------------------------------------------------------------------
__device__ __nv_bfloat16 g_xh[(size_t)T_LEN * B_SZ * I_SZ];
__device__ __nv_bfloat16 g_xl[(size_t)T_LEN * B_SZ * I_SZ];
__device__ __nv_bfloat16 g_h1h[(size_t)T_LEN * HB];   // layer0 output sequence (hi split)
__device__ __nv_bfloat16 g_h1l[(size_t)T_LEN * HB];   // layer0 output sequence (lo split)
__device__ float         g_G[(size_t)T_LEN * B_SZ * G3H];  // gate preactivations
__device__ __nv_bfloat16 g_ping_h[2 * HB];            // layer1 ping-pong hidden (hi)
__device__ __nv_bfloat16 g_ping_l[2 * HB];            // layer1 ping-pong hidden (lo)
__device__ float         g_hfinal[HB];                // last h2 (fp32) for FC
__device__ unsigned      g_flag[2][T_LEN * NGRP];     // per-(layer, t, batch-group) flags
// weight splits
__device__ __nv_bfloat16 g_Wih0h[G3H * I_SZ], g_Wih0l[G3H * I_SZ];
__device__ __nv_bfloat16 g_Whh0h[G3H * H_SZ], g_Whh0l[G3H * H_SZ];
__device__ __nv_bfloat16 g_Wih1h[G3H * H_SZ], g_Wih1l[G3H * H_SZ];
__device__ __nv_bfloat16 g_Whh1h[G3H * H_SZ], g_Whh1l[G3H * H_SZ];

// ---------------------------------------------------------------------------
// Helpers
// ---------------------------------------------------------------------------
__device__ __forceinline__ void split_bf16(float v, __nv_bfloat16& hi, __nv_bfloat16& lo) {
    __nv_bfloat16 h = __float2bfloat16(v);
    hi = h;
    lo = __float2bfloat16(v - __bfloat162float(h));
}

__device__ __forceinline__ void mma16816(float* c, const unsigned* a, const unsigned* b) {
    asm volatile(
        "mma.sync.aligned.m16n8k16.row.col.f32.bf16.bf16.f32 "
        "{%0,%1,%2,%3}, {%4,%5,%6,%7}, {%8,%9}, {%0,%1,%2,%3};\n"
        : "+f"(c[0]), "+f"(c[1]), "+f"(c[2]), "+f"(c[3])
        : "r"(a[0]), "r"(a[1]), "r"(a[2]), "r"(a[3]), "r"(b[0]), "r"(b[1]));
}

// A fragment (16x16) from global row-major [rows, ld], pre-offset to tile origin.
__device__ __forceinline__ void ldfragA(unsigned* a, const __nv_bfloat16* __restrict__ A, int ld) {
    int lane = threadIdx.x & 31;
    int g = lane >> 2, tq = lane & 3;
    const __nv_bfloat16* p = A + (size_t)g * ld + 2 * tq;
    a[0] = *reinterpret_cast<const unsigned*>(p);
    a[1] = *reinterpret_cast<const unsigned*>(p + (size_t)8 * ld);
    a[2] = *reinterpret_cast<const unsigned*>(p + 8);
    a[3] = *reinterpret_cast<const unsigned*>(p + (size_t)8 * ld + 8);
}

// B fragment (n=8, k=16) from global [N, K] row-major.
__device__ __forceinline__ void ldfragB(unsigned* b, const __nv_bfloat16* __restrict__ Bp, int ld) {
    int lane = threadIdx.x & 31;
    int g = lane >> 2, tq = lane & 3;
    const __nv_bfloat16* p = Bp + (size_t)g * ld + 2 * tq;
    b[0] = *reinterpret_cast<const unsigned*>(p);
    b[1] = *reinterpret_cast<const unsigned*>(p + 8);
}

// B fragment from pitched smem (row0 pre-offset to the warp's 8-row group).
__device__ __forceinline__ void ldfragB_s(unsigned* b, const __nv_bfloat16* p) {
    int lane = threadIdx.x & 31;
    int g = lane >> 2, tq = lane & 3;
    const __nv_bfloat16* q = p + g * WPITCH + 2 * tq;
    b[0] = *reinterpret_cast<const unsigned*>(q);
    b[1] = *reinterpret_cast<const unsigned*>(q + 8);
}

// ---------------------------------------------------------------------------
// Setup kernels
// ---------------------------------------------------------------------------
__global__ void k_zero() {
    int i = blockIdx.x * blockDim.x + threadIdx.x;
    if (i < 2 * T_LEN * NGRP) ((unsigned*)g_flag)[i] = 0u;
}

__global__ void k_dummy() {}

__global__ void k_split_w(const float* __restrict__ wih0, const float* __restrict__ whh0,
                          const float* __restrict__ wih1, const float* __restrict__ whh1) {
    const int n0 = G3H * I_SZ;
    const int n1 = G3H * H_SZ;
    const int total = n0 + 3 * n1;
    for (int i = blockIdx.x * blockDim.x + threadIdx.x; i < total; i += gridDim.x * blockDim.x) {
        if (i < n0) {
            split_bf16(wih0[i], g_Wih0h[i], g_Wih0l[i]);
        } else if (i < n0 + n1) {
            int j = i - n0;
            split_bf16(whh0[j], g_Whh0h[j], g_Whh0l[j]);
        } else if (i < n0 + 2 * n1) {
            int j = i - n0 - n1;
            split_bf16(wih1[j], g_Wih1h[j], g_Wih1l[j]);
        } else {
            int j = i - n0 - 2 * n1;
            split_bf16(whh1[j], g_Whh1h[j], g_Whh1l[j]);
        }
    }
}

__global__ void k_split_x(const float* __restrict__ x) {
    const int n = T_LEN * B_SZ * I_SZ;
    for (int i = blockIdx.x * blockDim.x + threadIdx.x; i < n; i += gridDim.x * blockDim.x) {
        split_bf16(x[i], g_xh[i], g_xl[i]);
    }
}

// ---------------------------------------------------------------------------
// Feedforward gate GEMM: G[M,768] = A[M,K] @ W^T + b_ih  (split bf16, 3-term)
// ---------------------------------------------------------------------------
__global__ void __launch_bounds__(256) k_gi(
    const __nv_bfloat16* __restrict__ Ah, const __nv_bfloat16* __restrict__ Al, int K,
    const __nv_bfloat16* __restrict__ Wh, const __nv_bfloat16* __restrict__ Wl,
    const float* __restrict__ bias, float* __restrict__ Gout) {
    int w = threadIdx.x >> 5;
    int lane = threadIdx.x & 31;
    int g = lane >> 2, tq = lane & 3;
    int m0 = blockIdx.x * 64 + (w >> 2) * 32;
    int nw = (w & 3) * 16;

#pragma unroll 1
    for (int nt = 0; nt < G3H / 64; nt++) {
        int n0 = nt * 64 + nw;
        float acc[2][2][4];
#pragma unroll
        for (int a = 0; a < 2; a++)
#pragma unroll
            for (int b = 0; b < 2; b++)
#pragma unroll
                for (int i = 0; i < 4; i++) acc[a][b][i] = 0.0f;

#pragma unroll 4
        for (int k = 0; k < K; k += 16) {
            unsigned aH[2][4], aL[2][4], bH[2][2], bL[2][2];
#pragma unroll
            for (int ms = 0; ms < 2; ms++) {
                ldfragA(aH[ms], Ah + (size_t)(m0 + ms * 16) * K + k, K);
                ldfragA(aL[ms], Al + (size_t)(m0 + ms * 16) * K + k, K);
            }
#pragma unroll
            for (int ns = 0; ns < 2; ns++) {
                ldfragB(bH[ns], Wh + (size_t)(n0 + ns * 8) * K + k, K);
                ldfragB(bL[ns], Wl + (size_t)(n0 + ns * 8) * K + k, K);
            }
#pragma unroll
            for (int ms = 0; ms < 2; ms++)
#pragma unroll
                for (int ns = 0; ns < 2; ns++) {
                    mma16816(acc[ms][ns], aH[ms], bH[ns]);
                    mma16816(acc[ms][ns], aH[ms], bL[ns]);
                    mma16816(acc[ms][ns], aL[ms], bH[ns]);
                }
        }

#pragma unroll
        for (int ms = 0; ms < 2; ms++)
#pragma unroll
            for (int ns = 0; ns < 2; ns++)
#pragma unroll
                for (int i = 0; i < 4; i++) {
                    int row = m0 + ms * 16 + g + ((i & 2) ? 8 : 0);
                    int col = n0 + ns * 8 + tq * 2 + (i & 1);
                    Gout[(size_t)row * G3H + col] = acc[ms][ns][i] + bias[col];
                }
    }
}

// ---------------------------------------------------------------------------
// Persistent GRU recurrence. Grid: 64 CTAs = 4 batch-groups x 16 hidden blocks.
// 256 threads (8 warps: 4 batch-quarters x 2 hidden-halves).
// CTA tile: 64 batch x 16 hidden x 3 gates. Weights smem-resident (loaded once).
// Sync: per-(t, batch-group) 16-CTA flag (release/acquire through L2).
// ---------------------------------------------------------------------------
__global__ void __launch_bounds__(256) k_rec(
    const float* __restrict__ G,
    const __nv_bfloat16* __restrict__ Wh, const __nv_bfloat16* __restrict__ Wl,  // [768,256]
    const float* __restrict__ b_hh,
    __nv_bfloat16* __restrict__ bufh, __nv_bfloat16* __restrict__ bufl,
    int seq_mode,                           // 1: buf indexed by t; 0: ping-pong
    float* __restrict__ hfinal,             // null or [B,H]
    unsigned* __restrict__ flags) {         // [T, NGRP]
    extern __shared__ __nv_bfloat16 s_w[];  // [6][16][WPITCH]: (gate*2+split)

    const int tid = threadIdx.x;
    const int w = tid >> 5, lane = tid & 31;
    const int g = lane >> 2, tq = lane & 3;
    const int bb = blockIdx.x >> 4;          // 0..3 batch group (64 rows)
    const int jb = blockIdx.x & 15;          // 0..15 hidden block (16 units)
    const int mq = w >> 1, nh = w & 1;
    const int m0 = bb * 64 + mq * 16;
    const int j0 = jb * 16 + nh * 8;
    const int c0 = j0 + tq * 2;
    const int row_lo = m0 + g, row_hi = m0 + g + 8;

    // ---- stage this CTA's weight slice into smem (once) ----
#pragma unroll 1
    for (int s = 0; s < 2; s++) {
        const __nv_bfloat16* Wsrc = s ? Wl : Wh;
#pragma unroll 1
        for (int gate = 0; gate < 3; gate++) {
            const unsigned* src = reinterpret_cast<const unsigned*>(
                Wsrc + (size_t)(gate * H_SZ + jb * 16) * H_SZ);
            __nv_bfloat16* dst = s_w + (size_t)(gate * 2 + s) * 16 * WPITCH;
            for (int idx = tid; idx < 16 * 128; idx += 256) {
                int r = idx >> 7, cu = idx & 127;
                *reinterpret_cast<unsigned*>(dst + r * WPITCH + cu * 2) = src[r * 128 + cu];
            }
        }
    }
    __syncthreads();

    // per-thread b_hh for its two columns
    float bR[2] = {b_hh[c0], b_hh[c0 + 1]};
    float bZ[2] = {b_hh[H_SZ + c0], b_hh[H_SZ + c0 + 1]};
    float bN[2] = {b_hh[2 * H_SZ + c0], b_hh[2 * H_SZ + c0 + 1]};

    float hprev[4] = {0.0f, 0.0f, 0.0f, 0.0f};

#pragma unroll 1
    for (int t = 0; t < T_LEN; t++) {
        // ---- prefetch gate preactivations (independent of h; hides DRAM) ----
        const float* Gt = G + (size_t)t * B_SZ * G3H;
        float gir[4], giz[4], gin[4];
#pragma unroll
        for (int i = 0; i < 4; i++) {
            int row = (i & 2) ? row_hi : row_lo;
            const float* p = Gt + (size_t)row * G3H + c0 + (i & 1);
            gir[i] = __ldg(p);
            giz[i] = __ldg(p + H_SZ);
            gin[i] = __ldg(p + 2 * H_SZ);
        }

        // ---- wait for previous step of this batch group ----
        if (t > 0) {
            if (tid == 0) {
                const unsigned* fp = flags + (size_t)(t - 1) * NGRP + bb;
                unsigned v;
                do {
                    asm volatile("ld.acquire.gpu.global.u32 %0, [%1];" : "=r"(v) : "l"(fp));
                } while (v < GRP_CTAS);
            }
            __syncthreads();
        }

        float accR[4] = {0, 0, 0, 0}, accZ[4] = {0, 0, 0, 0}, accN[4] = {0, 0, 0, 0};
        if (t > 0) {
            const __nv_bfloat16* hin_h;
            const __nv_bfloat16* hin_l;
            if (seq_mode) {
                hin_h = bufh + (size_t)(t - 1) * HB;
                hin_l = bufl + (size_t)(t - 1) * HB;
            } else {
                hin_h = bufh + (size_t)((t - 1) & 1) * HB;
                hin_l = bufl + (size_t)((t - 1) & 1) * HB;
            }
#pragma unroll 4
            for (int k = 0; k < H_SZ; k += 16) {
                unsigned ah[4], al[4];
                ldfragA(ah, hin_h + (size_t)m0 * H_SZ + k, H_SZ);
                ldfragA(al, hin_l + (size_t)m0 * H_SZ + k, H_SZ);
                unsigned bRh[2], bRl[2], bZh[2], bZl[2], bNh[2], bNl[2];
                const __nv_bfloat16* base = s_w + nh * 8 * WPITCH + k;
                ldfragB_s(bRh, base + (size_t)(0 * 2 + 0) * 16 * WPITCH);
                ldfragB_s(bRl, base + (size_t)(0 * 2 + 1) * 16 * WPITCH);
                ldfragB_s(bZh, base + (size_t)(1 * 2 + 0) * 16 * WPITCH);
                ldfragB_s(bZl, base + (size_t)(1 * 2 + 1) * 16 * WPITCH);
                ldfragB_s(bNh, base + (size_t)(2 * 2 + 0) * 16 * WPITCH);
                ldfragB_s(bNl, base + (size_t)(2 * 2 + 1) * 16 * WPITCH);
                mma16816(accR, ah, bRh); mma16816(accR, ah, bRl); mma16816(accR, al, bRh);
                mma16816(accZ, ah, bZh); mma16816(accZ, ah, bZl); mma16816(accZ, al, bZh);
                mma16816(accN, ah, bNh); mma16816(accN, ah, bNl); mma16816(accN, al, bNh);
            }
        }

        // ---- fused pointwise GRU update ----
        __nv_bfloat16* hout_h;
        __nv_bfloat16* hout_l;
        if (seq_mode) {
            hout_h = bufh + (size_t)t * HB;
            hout_l = bufl + (size_t)t * HB;
        } else {
            hout_h = bufh + (size_t)(t & 1) * HB;
            hout_l = bufl + (size_t)(t & 1) * HB;
        }
        float v[4];
#pragma unroll
        for (int i = 0; i < 4; i++) {
            float hr = accR[i] + bR[i & 1];
            float hz = accZ[i] + bZ[i & 1];
            float hn = accN[i] + bN[i & 1];
            float r = 1.0f / (1.0f + expf(-(gir[i] + hr)));
            float z = 1.0f / (1.0f + expf(-(giz[i] + hz)));
            float n = tanhf(gin[i] + r * hn);
            v[i] = (1.0f - z) * n + z * hprev[i];
            hprev[i] = v[i];
        }
        // packed bf16x2 stores (cols c0, c0+1 contiguous)
#pragma unroll
        for (int half = 0; half < 2; half++) {
            int row = half ? row_hi : row_lo;
            float v0 = v[half * 2 + 0], v1 = v[half * 2 + 1];
            __nv_bfloat16 h0, l0, h1, l1;
            split_bf16(v0, h0, l0);
            split_bf16(v1, h1, l1);
            size_t o = (size_t)row * H_SZ + c0;
            *reinterpret_cast<__nv_bfloat162*>(hout_h + o) = __nv_bfloat162(h0, h1);
            *reinterpret_cast<__nv_bfloat162*>(hout_l + o) = __nv_bfloat162(l0, l1);
            if (hfinal != nullptr && t == T_LEN - 1) {
                hfinal[o] = v0;
                hfinal[o + 1] = v1;
            }
        }

        // ---- arrive ----
        __syncthreads();
        if (tid == 0) {
            asm volatile("red.release.gpu.global.add.u32 [%0], 1;"
                         :: "l"(flags + (size_t)t * NGRP + bb) : "memory");
        }
    }
}

// ---------------------------------------------------------------------------
// Final FC: out[B,H] = h2 @ W_fc^T + b_fc
// ---------------------------------------------------------------------------
__global__ void __launch_bounds__(256) k_fc(const float* __restrict__ Wfc,
                                            const float* __restrict__ bfc,
                                            float* __restrict__ out) {
    __shared__ float hrow[H_SZ];
    int b_ = blockIdx.x, j = threadIdx.x;
    hrow[j] = g_hfinal[(size_t)b_ * H_SZ + j];
    __syncthreads();
    const float* wr = Wfc + (size_t)j * H_SZ;
    float s = bfc[j];
#pragma unroll 8
    for (int k = 0; k < H_SZ; k++) s += hrow[k] * wr[k];
    out[(size_t)b_ * H_SZ + j] = s;
}

// ---------------------------------------------------------------------------
// Launch
// ---------------------------------------------------------------------------
extern "C" void kernel_launch(void* const* d_in, const int* in_sizes, int n_in,
                              void* d_out, int out_size) {
    const float* x    = (const float*)d_in[0];
    const float* Wih0 = (const float*)d_in[1];
    const float* Whh0 = (const float*)d_in[2];
    const float* bih0 = (const float*)d_in[3];
    const float* bhh0 = (const float*)d_in[4];
    const float* Wih1 = (const float*)d_in[5];
    const float* Whh1 = (const float*)d_in[6];
    const float* bih1 = (const float*)d_in[7];
    const float* bhh1 = (const float*)d_in[8];
    const float* Wfc  = (const float*)d_in[9];
    const float* bfc  = (const float*)d_in[10];
    (void)in_sizes; (void)n_in; (void)out_size;

    static int smem_set = 0;
    if (!smem_set) {
        cudaFuncSetAttribute(k_rec, cudaFuncAttributeMaxDynamicSharedMemorySize, SMEM_REC_BYTES);
        smem_set = 1;
    }

    void *p_xh, *p_xl, *p_h1h, *p_h1l, *p_G, *p_ph, *p_pl, *p_hf, *p_fl;
    void *p_Wih0h, *p_Wih0l, *p_Whh0h, *p_Whh0l, *p_Wih1h, *p_Wih1l, *p_Whh1h, *p_Whh1l;
    cudaGetSymbolAddress(&p_xh, g_xh);       cudaGetSymbolAddress(&p_xl, g_xl);
    cudaGetSymbolAddress(&p_h1h, g_h1h);     cudaGetSymbolAddress(&p_h1l, g_h1l);
    cudaGetSymbolAddress(&p_G, g_G);
    cudaGetSymbolAddress(&p_ph, g_ping_h);   cudaGetSymbolAddress(&p_pl, g_ping_l);
    cudaGetSymbolAddress(&p_hf, g_hfinal);   cudaGetSymbolAddress(&p_fl, g_flag);
    cudaGetSymbolAddress(&p_Wih0h, g_Wih0h); cudaGetSymbolAddress(&p_Wih0l, g_Wih0l);
    cudaGetSymbolAddress(&p_Whh0h, g_Whh0h); cudaGetSymbolAddress(&p_Whh0l, g_Whh0l);
    cudaGetSymbolAddress(&p_Wih1h, g_Wih1h); cudaGetSymbolAddress(&p_Wih1l, g_Wih1l);
    cudaGetSymbolAddress(&p_Whh1h, g_Whh1h); cudaGetSymbolAddress(&p_Whh1l, g_Whh1l);

    typedef __nv_bfloat16 bf;
    float* G = (float*)p_G;
    unsigned* fl0 = (unsigned*)p_fl;
    unsigned* fl1 = fl0 + T_LEN * NGRP;

    // launch order chosen so ncu (-s 5 -c 1) profiles k_rec layer 0
    k_zero<<<8, 512>>>();                                            // 0
    k_split_w<<<512, 256>>>(Wih0, Whh0, Wih1, Whh1);                 // 1
    k_split_x<<<2048, 256>>>(x);                                     // 2
    k_gi<<<T_LEN * B_SZ / 64, 256>>>((bf*)p_xh, (bf*)p_xl, I_SZ,
                                     (bf*)p_Wih0h, (bf*)p_Wih0l, bih0, G);  // 3
    k_dummy<<<1, 32>>>();                                            // 4
    k_rec<<<NGRP * GRP_CTAS, 256, SMEM_REC_BYTES>>>(                 // 5  <- profiled
        G, (bf*)p_Whh0h, (bf*)p_Whh0l, bhh0,
        (bf*)p_h1h, (bf*)p_h1l, /*seq_mode=*/1, nullptr, fl0);
    k_gi<<<T_LEN * B_SZ / 64, 256>>>((bf*)p_h1h, (bf*)p_h1l, H_SZ,
                                     (bf*)p_Wih1h, (bf*)p_Wih1l, bih1, G);  // 6
    k_rec<<<NGRP * GRP_CTAS, 256, SMEM_REC_BYTES>>>(                 // 7
        G, (bf*)p_Whh1h, (bf*)p_Whh1l, bhh1,
        (bf*)p_ph, (bf*)p_pl, /*seq_mode=*/0, (float*)p_hf, fl1);
    k_fc<<<B_SZ, H_SZ>>>(Wfc, bfc, (float*)d_out);                   // 8
}